// round 2
// baseline (speedup 1.0000x reference)
#include <cuda_runtime.h>
#include <cuda_bf16.h>

#define BATCH 8
#define CC    64
#define DD    8
#define NPIX  4096

// ---------------- device scratch (no cudaMalloc allowed) ----------------
__device__ float g_Q[BATCH * NPIX * DD];    // [b][n][d]   1 MB
__device__ float g_K[BATCH * NPIX * DD];    // [b][m][d]   1 MB
__device__ float g_V[BATCH * NPIX * CC];    // [b][m][c]   8 MB
__device__ float g_Zp[4 * BATCH * NPIX];    // [split][b][m] partial Z sums
__device__ float g_part[BATCH * CC * NPIX]; // m-split partial output (8 MB)

typedef unsigned long long u64;

__device__ __forceinline__ void ffma2(u64 &d, u64 a, u64 b) {
    asm("fma.rn.f32x2 %0, %1, %2, %0;" : "+l"(d) : "l"(a), "l"(b));
}
__device__ __forceinline__ u64 pack2(float lo, float hi) {
    u64 r; asm("mov.b64 %0, {%1, %2};" : "=l"(r) : "f"(lo), "f"(hi)); return r;
}
__device__ __forceinline__ float2 unpack2(u64 v) {
    float lo, hi; asm("mov.b64 {%0, %1}, %2;" : "=f"(lo), "=f"(hi) : "l"(v));
    return make_float2(lo, hi);
}

// ---------------- 1: per-pixel projections (1x1 convs) ----------------
__global__ void __launch_bounds__(256) proj_kernel(
    const float* __restrict__ x,
    const float* __restrict__ Wq, const float* __restrict__ bq,
    const float* __restrict__ Wk, const float* __restrict__ bk,
    const float* __restrict__ Wv, const float* __restrict__ bv)
{
    __shared__ float sWqT[CC * DD];   // [c][d]
    __shared__ float sWkT[CC * DD];   // [c][d]
    __shared__ float sWvT[CC * CC];   // [c][d_out]
    const int tid = threadIdx.x;
    const int b = blockIdx.y;
    const int n = blockIdx.x * 256 + tid;

    for (int i = tid; i < CC * DD; i += 256) {
        int d = i >> 6, c = i & 63;
        sWqT[c * DD + d] = Wq[i];
        sWkT[c * DD + d] = Wk[i];
    }
    for (int i = tid; i < CC * CC; i += 256) {
        int d = i >> 6, c = i & 63;
        sWvT[c * CC + d] = Wv[i];
    }
    __syncthreads();

    float q[DD], k[DD], v[CC];
#pragma unroll
    for (int d = 0; d < DD; d++) { q[d] = 0.f; k[d] = 0.f; }
#pragma unroll
    for (int d = 0; d < CC; d++) v[d] = 0.f;

    const float* xp = x + (b * CC) * NPIX + n;
#pragma unroll 1
    for (int c = 0; c < CC; c++) {
        float xc = xp[c * NPIX];                  // coalesced across threads
        const float* wq = sWqT + c * DD;
        const float* wk = sWkT + c * DD;
        const float* wv = sWvT + c * CC;
#pragma unroll
        for (int d = 0; d < DD; d++) {
            q[d] = fmaf(wq[d], xc, q[d]);
            k[d] = fmaf(wk[d], xc, k[d]);
        }
#pragma unroll
        for (int d = 0; d < CC; d++) v[d] = fmaf(wv[d], xc, v[d]);
    }

    float* qo = g_Q + ((b << 12) + n) * DD;
    float* ko = g_K + ((b << 12) + n) * DD;
#pragma unroll
    for (int d = 0; d < DD; d++) {
        qo[d] = q[d] + __ldg(bq + d);
        ko[d] = k[d] + __ldg(bk + d);
    }
    float* vo = g_V + ((b << 12) + n) * CC;
#pragma unroll
    for (int d = 0; d < CC; d++) vo[d] = v[d] + __ldg(bv + d);
}

// ---------------- 2: column sums Z[m] = sum_n exp(s[n,m]) ----------------
// grid (M/128, 4 n-splits, B), 128 threads; deterministic (no atomics).
__global__ void __launch_bounds__(128) zr_kernel()
{
    const int tid = threadIdx.x;
    const int b = blockIdx.z;
    const int ns = blockIdx.y;
    const int m = blockIdx.x * 128 + tid;

    const float4* kp = (const float4*)(g_K + ((b << 12) + m) * DD);
    const float4 ka = kp[0], kb = kp[1];

    __shared__ float4 sQ[256];   // 128 query vectors
    float z0 = 0.f, z1 = 0.f;

    for (int t = 0; t < 8; t++) {
        const int nb = ns * 1024 + t * 128;
        __syncthreads();
        const float4* qg = (const float4*)(g_Q + ((b << 12) + nb) * DD);
        sQ[tid] = qg[tid];
        sQ[tid + 128] = qg[tid + 128];
        __syncthreads();
#pragma unroll 4
        for (int nl = 0; nl < 128; nl += 2) {
            float4 qa = sQ[nl * 2],     qb = sQ[nl * 2 + 1];
            float4 qc = sQ[nl * 2 + 2], qd = sQ[nl * 2 + 3];
            float s0 = ka.x*qa.x + ka.y*qa.y + ka.z*qa.z + ka.w*qa.w
                     + kb.x*qb.x + kb.y*qb.y + kb.z*qb.z + kb.w*qb.w;
            float s1 = ka.x*qc.x + ka.y*qc.y + ka.z*qc.z + ka.w*qc.w
                     + kb.x*qd.x + kb.y*qd.y + kb.z*qd.z + kb.w*qd.w;
            z0 += __expf(s0 * 0.125f);
            z1 += __expf(s1 * 0.125f);
        }
    }
    g_Zp[(ns * BATCH + b) * NPIX + m] = z0 + z1;
}

// ---------------- 3: fused out[c,n] = sum_m (V[c,m]/Z[m]) * exp(s[n,m]) ----------------
// grid (32 n-tiles, 2 m-splits, B), 256 threads.
// smem: sQ[128][8] | sK[64][8] | sV[64][64] | sP[64][128] | sRz[64]
#define OUT_SMEM (13888 * 4)

__global__ void __launch_bounds__(256, 2) out_kernel(float* __restrict__ out)
{
    extern __shared__ float sm[];
    float* sQ  = sm;            // 1024
    float* sK  = sm + 1024;     // 512
    float* sV  = sm + 1536;     // 4096
    float* sP  = sm + 5632;     // 8192
    float* sRz = sm + 13824;    // 64

    const int tid = threadIdx.x;
    const int b  = blockIdx.z;
    const int ms = blockIdx.y;
    const int n_base = blockIdx.x * 128;

    // load 128 query vectors once
    const float4* qg = (const float4*)(g_Q + ((b << 12) + n_base) * DD);
    ((float4*)sQ)[tid] = qg[tid];

    u64 acc[16];
#pragma unroll
    for (int i = 0; i < 16; i++) acc[i] = 0ULL;

    const int c0 = (tid >> 4) * 4;     // phase-B c group (4)
    const int n0 = (tid & 15) * 8;     // phase-B n group (8)
    const int am0 = (tid >> 4) * 4;    // phase-A m group (4)
    const int an0 = (tid & 15) * 8;    // phase-A n group (8)

    for (int mt = 0; mt < 32; mt++) {                // FIX R1: was 16 -> dropped half the m range
        const int m_base = ms * 2048 + mt * 64;
        __syncthreads();   // prev phase B done; sQ ready on iter 0

        // segment 1: load K tile + reciprocal Z
        if (tid < 128)
            ((float4*)sK)[tid] =
                ((const float4*)(g_K + ((b << 12) + m_base) * DD))[tid];
        if (tid < 64) {
            const int m = m_base + tid;
            float z = g_Zp[(0 * BATCH + b) * NPIX + m]
                    + g_Zp[(1 * BATCH + b) * NPIX + m]
                    + g_Zp[(2 * BATCH + b) * NPIX + m]
                    + g_Zp[(3 * BATCH + b) * NPIX + m];
            sRz[tid] = 1.0f / z;
        }
        __syncthreads();

        // segment 2a: load V tile scaled by 1/Z
        const float4* vg = (const float4*)(g_V + ((b << 12) + m_base) * CC);
#pragma unroll
        for (int kk = 0; kk < 4; kk++) {
            int j = kk * 256 + tid;        // 1024 float4s
            float4 t = vg[j];
            float r = sRz[j >> 4];
            t.x *= r; t.y *= r; t.z *= r; t.w *= r;
            ((float4*)sV)[j] = t;
        }

        // segment 2b: phase A — scores + exp into sP[m][n]
#pragma unroll
        for (int mi = 0; mi < 4; mi++) {
            const int m = am0 + mi;
            const float4 ka = *(const float4*)(sK + m * 8);
            const float4 kb = *(const float4*)(sK + m * 8 + 4);
            float e[8];
#pragma unroll
            for (int nj = 0; nj < 8; nj++) {
                const float* qp = sQ + (an0 + nj) * 8;
                float4 qa = *(const float4*)(qp);
                float4 qb = *(const float4*)(qp + 4);
                float s = ka.x*qa.x + ka.y*qa.y + ka.z*qa.z + ka.w*qa.w
                        + kb.x*qb.x + kb.y*qb.y + kb.z*qb.z + kb.w*qb.w;
                e[nj] = __expf(s * 0.125f);
            }
            *(float4*)(sP + m * 128 + an0)     = make_float4(e[0], e[1], e[2], e[3]);
            *(float4*)(sP + m * 128 + an0 + 4) = make_float4(e[4], e[5], e[6], e[7]);
        }
        __syncthreads();

        // segment 3: phase B — rank-1 accumulate with packed f32x2 FMA
#pragma unroll 4
        for (int m = 0; m < 64; m++) {
            float4 v4 = *(const float4*)(sV + m * 64 + c0);
            float4 p0 = *(const float4*)(sP + m * 128 + n0);
            float4 p1 = *(const float4*)(sP + m * 128 + n0 + 4);
            u64 bp0 = pack2(p0.x, p0.y), bp1 = pack2(p0.z, p0.w);
            u64 bp2 = pack2(p1.x, p1.y), bp3 = pack2(p1.z, p1.w);
            u64 va;
            va = pack2(v4.x, v4.x);
            ffma2(acc[0], va, bp0); ffma2(acc[1], va, bp1);
            ffma2(acc[2], va, bp2); ffma2(acc[3], va, bp3);
            va = pack2(v4.y, v4.y);
            ffma2(acc[4], va, bp0); ffma2(acc[5], va, bp1);
            ffma2(acc[6], va, bp2); ffma2(acc[7], va, bp3);
            va = pack2(v4.z, v4.z);
            ffma2(acc[8], va, bp0); ffma2(acc[9], va, bp1);
            ffma2(acc[10], va, bp2); ffma2(acc[11], va, bp3);
            va = pack2(v4.w, v4.w);
            ffma2(acc[12], va, bp0); ffma2(acc[13], va, bp1);
            ffma2(acc[14], va, bp2); ffma2(acc[15], va, bp3);
        }
    }

    // epilogue: split 0 -> d_out, split 1 -> g_part (summed by add_kernel)
    float* dst = (ms == 0) ? out : g_part;
#pragma unroll
    for (int i = 0; i < 4; i++) {
        float2 a0 = unpack2(acc[i * 4 + 0]);
        float2 a1 = unpack2(acc[i * 4 + 1]);
        float2 a2 = unpack2(acc[i * 4 + 2]);
        float2 a3 = unpack2(acc[i * 4 + 3]);
        float* op = dst + ((size_t)(b * CC + c0 + i) << 12) + n_base + n0;
        *(float4*)(op)     = make_float4(a0.x, a0.y, a1.x, a1.y);
        *(float4*)(op + 4) = make_float4(a2.x, a2.y, a3.x, a3.y);
    }
}

// ---------------- 4: combine m-split partials ----------------
__global__ void __launch_bounds__(256) add_kernel(float* __restrict__ out)
{
    int i = blockIdx.x * 256 + threadIdx.x;
    float4* o = (float4*)out;
    const float4* p = (const float4*)g_part;
    float4 a = o[i], q = p[i];
    a.x += q.x; a.y += q.y; a.z += q.z; a.w += q.w;
    o[i] = a;
}

// ---------------- launch ----------------
extern "C" void kernel_launch(void* const* d_in, const int* in_sizes, int n_in,
                              void* d_out, int out_size)
{
    const float* x  = (const float*)d_in[0];
    const float* Wq = (const float*)d_in[1];
    const float* bq = (const float*)d_in[2];
    const float* Wk = (const float*)d_in[3];
    const float* bk = (const float*)d_in[4];
    const float* Wv = (const float*)d_in[5];
    const float* bv = (const float*)d_in[6];
    float* out = (float*)d_out;

    cudaFuncSetAttribute(out_kernel, cudaFuncAttributeMaxDynamicSharedMemorySize, OUT_SMEM);

    proj_kernel<<<dim3(16, BATCH), 256>>>(x, Wq, bq, Wk, bk, Wv, bv);
    zr_kernel<<<dim3(32, 4, BATCH), 128>>>();
    out_kernel<<<dim3(32, 2, BATCH), 256, OUT_SMEM>>>(out);
    add_kernel<<<2048, 256>>>(out);
}